// round 2
// baseline (speedup 1.0000x reference)
#include <cuda_runtime.h>
#include <math.h>

// ---------------------------------------------------------------------------
// Fused update kernel:
//   u = vec @ U^T (per xyz), v = vec @ V^T, vnorm = ||v||, m=[s,vnorm]
//   h = silu(m@W1^T+b1), mm = h@W2^T+b2 -> (a,b,c)
//   delta_v = u*a ; delta_s = b + c*(u.v)
// Layout: out[0 .. N*C*3) = delta_v row-major [N,C,3]; then delta_s [N,C].
// ---------------------------------------------------------------------------

#define CC 128
#define RB 32            // rows per block
#define NTHREADS 256

// shared memory float offsets
#define OFF_A   0        // Xs (128 x 96) phase1; aliased as mm (32 x 385) phase3+
#define OFF_US  12320    // us[m][c], stride 132, m = i*32+r  (96 x 132)
#define OFF_VS  24992
#define OFF_MS  37664    // ms[k][r], stride 33 (256 x 33)
#define OFF_HS  46112    // hs[o][r], stride 33 (128 x 33)
#define SMEM_FLOATS 50336
#define SMEM_BYTES (SMEM_FLOATS * 4)

// transposed weights (scratch; __device__ globals are the allowed scratch path)
__device__ float g_Ut[CC * CC];          // Ut[c][o] = U[o][c]
__device__ float g_Vt[CC * CC];
__device__ float g_W1t[2 * CC * CC];     // W1t[k][o] = W1[o][k], k<256,o<128
__device__ float g_W2t[CC * 3 * CC];     // W2t[k][o] = W2[o][k], k<128,o<384

typedef unsigned long long ull;

__device__ __forceinline__ void fma2(ull& d, ull a, ull b) {
    asm("fma.rn.f32x2 %0, %1, %2, %0;" : "+l"(d) : "l"(a), "l"(b));
}
__device__ __forceinline__ ull splat2(float x) {
    ull r; asm("mov.b64 %0, {%1, %1};" : "=l"(r) : "f"(x)); return r;
}
__device__ __forceinline__ float2 unpack2(ull v) {
    float2 f; asm("mov.b64 {%0, %1}, %2;" : "=f"(f.x), "=f"(f.y) : "l"(v)); return f;
}

// ---------------------------------------------------------------------------
__global__ void prep_kernel(const float* __restrict__ U, const float* __restrict__ V,
                            const float* __restrict__ W1, const float* __restrict__ W2) {
    int idx = blockIdx.x * blockDim.x + threadIdx.x;
    if (idx < 16384) {
        int c = idx >> 7, o = idx & 127;
        g_Ut[idx] = U[o * CC + c];
    } else if (idx < 32768) {
        int t = idx - 16384; int c = t >> 7, o = t & 127;
        g_Vt[t] = V[o * CC + c];
    } else if (idx < 65536) {
        int t = idx - 32768; int k = t >> 7, o = t & 127;
        g_W1t[t] = W1[o * 256 + k];
    } else if (idx < 114688) {
        int t = idx - 65536; int k = t / 384, o = t % 384;
        g_W2t[t] = W2[o * CC + k];
    }
}

// ---------------------------------------------------------------------------
__global__ __launch_bounds__(NTHREADS, 1)
void fused_update_kernel(const float* __restrict__ vec,
                         const float* __restrict__ sca,
                         const float* __restrict__ b1g,
                         const float* __restrict__ b2g,
                         float* __restrict__ out,
                         int nrows) {
    extern __shared__ float sm[];
    float* Xs = sm + OFF_A;   // Xs[c*96 + (i*32+r)] ; later mm[r*385+o]
    float* us = sm + OFF_US;  // us[m*132 + c]
    float* vs = sm + OFF_VS;
    float* ms = sm + OFF_MS;  // ms[k*33 + r]
    float* hs = sm + OFF_HS;  // hs[o*33 + r]

    const int tid = threadIdx.x;
    const int tx = tid & 31, ty = tid >> 5;
    const int row0 = blockIdx.x * RB;

    // ---- stage vec tile into Xs (transposed, components split) + scalar into ms
    {
        const float4* vg = (const float4*)(vec + (size_t)row0 * 384);
        for (int idx = tid; idx < RB * 96; idx += NTHREADS) {
            int r = idx / 96, q = idx - r * 96;
            float4 f = vg[r * 96 + q];
            float vals[4] = {f.x, f.y, f.z, f.w};
            int e0 = q * 4;
#pragma unroll
            for (int j = 0; j < 4; j++) {
                int e = e0 + j; int c = e / 3, i = e - 3 * c;
                Xs[c * 96 + i * 32 + r] = vals[j];
            }
        }
        for (int idx = tid; idx < RB * CC; idx += NTHREADS) {
            int r = idx >> 7, k = idx & 127;
            ms[k * 33 + r] = sca[(size_t)(row0 + r) * CC + k];
        }
    }
    __syncthreads();

    // ---- Phase 1: u,v = X @ {Ut,Vt}.  M=96 (ty: 12 rows), Nc=128 (tx: 4 cols)
    {
        const int m0 = ty * 12, c0 = tx * 4;
        ull aU[4][6], aV[4][6];
#pragma unroll
        for (int i = 0; i < 4; i++)
#pragma unroll
            for (int j = 0; j < 6; j++) { aU[i][j] = 0ull; aV[i][j] = 0ull; }

        float4 bu = __ldg((const float4*)(g_Ut + c0));
        float4 bv = __ldg((const float4*)(g_Vt + c0));
#pragma unroll 2
        for (int k = 0; k < CC; k++) {
            float4 bun = bu, bvn = bv;
            if (k + 1 < CC) {
                bun = __ldg((const float4*)(g_Ut + (k + 1) * CC + c0));
                bvn = __ldg((const float4*)(g_Vt + (k + 1) * CC + c0));
            }
            const ull* xr = (const ull*)(Xs + k * 96 + m0);  // 12 floats = 6 packed pairs
            ull av[6] = {xr[0], xr[1], xr[2], xr[3], xr[4], xr[5]};
            ull su[4] = {splat2(bu.x), splat2(bu.y), splat2(bu.z), splat2(bu.w)};
            ull sv[4] = {splat2(bv.x), splat2(bv.y), splat2(bv.z), splat2(bv.w)};
#pragma unroll
            for (int c = 0; c < 4; c++)
#pragma unroll
                for (int j = 0; j < 6; j++) {
                    fma2(aU[c][j], av[j], su[c]);
                    fma2(aV[c][j], av[j], sv[c]);
                }
            bu = bun; bv = bvn;
        }
#pragma unroll
        for (int c = 0; c < 4; c++)
#pragma unroll
            for (int j = 0; j < 6; j++) {
                float2 fu = unpack2(aU[c][j]), fv = unpack2(aV[c][j]);
                int m = m0 + 2 * j;
                us[m * 132 + c0 + c] = fu.x; us[(m + 1) * 132 + c0 + c] = fu.y;
                vs[m * 132 + c0 + c] = fv.x; vs[(m + 1) * 132 + c0 + c] = fv.y;
            }
    }
    __syncthreads();

    // ---- vnorm -> ms[128..255]
    for (int idx = tid; idx < RB * CC; idx += NTHREADS) {
        int r = idx >> 7, c = idx & 127;
        float v0 = vs[r * 132 + c];
        float v1 = vs[(32 + r) * 132 + c];
        float v2 = vs[(64 + r) * 132 + c];
        ms[(128 + c) * 33 + r] = sqrtf(v0 * v0 + v1 * v1 + v2 * v2 + 1e-8f);
    }
    __syncthreads();

    // ---- Phase 2: h = silu(m @ W1t + b1). out [32 x 128]; tx: 4 cols, ty: 4 rows
    {
        const int c0 = tx * 4, r0 = ty * 4;
        ull acc[4][2];
#pragma unroll
        for (int i = 0; i < 4; i++) { acc[i][0] = 0ull; acc[i][1] = 0ull; }

        ulonglong2 b = __ldg((const ulonglong2*)(g_W1t + c0));
#pragma unroll 2
        for (int k = 0; k < 2 * CC; k++) {
            ulonglong2 bn = b;
            if (k + 1 < 2 * CC) bn = __ldg((const ulonglong2*)(g_W1t + (k + 1) * CC + c0));
            const float* mr = ms + k * 33 + r0;
            ull s0 = splat2(mr[0]), s1 = splat2(mr[1]), s2 = splat2(mr[2]), s3 = splat2(mr[3]);
            fma2(acc[0][0], s0, b.x); fma2(acc[0][1], s0, b.y);
            fma2(acc[1][0], s1, b.x); fma2(acc[1][1], s1, b.y);
            fma2(acc[2][0], s2, b.x); fma2(acc[2][1], s2, b.y);
            fma2(acc[3][0], s3, b.x); fma2(acc[3][1], s3, b.y);
            b = bn;
        }
        float4 bias = __ldg((const float4*)(b1g + c0));
        float bb[4] = {bias.x, bias.y, bias.z, bias.w};
#pragma unroll
        for (int rr = 0; rr < 4; rr++) {
            float2 p0 = unpack2(acc[rr][0]), p1 = unpack2(acc[rr][1]);
            float xv[4] = {p0.x + bb[0], p0.y + bb[1], p1.x + bb[2], p1.y + bb[3]};
#pragma unroll
            for (int j = 0; j < 4; j++) {
                float x = xv[j];
                float h = x / (1.0f + __expf(-x));
                hs[(c0 + j) * 33 + (r0 + rr)] = h;
            }
        }
    }
    __syncthreads();

    // ---- Phase 3: mm = h @ W2t + b2. out [32 x 384]; tx: 12 cols, ty: 4 rows
    {
        const int o0 = tx * 12, r0 = ty * 4;
        ull acc[4][6];
#pragma unroll
        for (int i = 0; i < 4; i++)
#pragma unroll
            for (int j = 0; j < 6; j++) acc[i][j] = 0ull;

        const ulonglong2* w0p = (const ulonglong2*)(g_W2t + o0);
        ulonglong2 w0 = __ldg(w0p), w1 = __ldg(w0p + 1), w2 = __ldg(w0p + 2);
#pragma unroll 2
        for (int k = 0; k < CC; k++) {
            ulonglong2 n0 = w0, n1 = w1, n2 = w2;
            if (k + 1 < CC) {
                const ulonglong2* wp = (const ulonglong2*)(g_W2t + (k + 1) * 384 + o0);
                n0 = __ldg(wp); n1 = __ldg(wp + 1); n2 = __ldg(wp + 2);
            }
            const float* hr = hs + k * 33 + r0;
            ull s[4] = {splat2(hr[0]), splat2(hr[1]), splat2(hr[2]), splat2(hr[3])};
            ull bw[6] = {w0.x, w0.y, w1.x, w1.y, w2.x, w2.y};
#pragma unroll
            for (int rr = 0; rr < 4; rr++)
#pragma unroll
                for (int p = 0; p < 6; p++) fma2(acc[rr][p], s[rr], bw[p]);
            w0 = n0; w1 = n1; w2 = n2;
        }
        float* mm = Xs;  // alias (Xs dead after phase-1 barrier)
        float bb[12];
#pragma unroll
        for (int p = 0; p < 3; p++) {
            float4 f = __ldg((const float4*)(b2g + o0 + p * 4));
            bb[p * 4 + 0] = f.x; bb[p * 4 + 1] = f.y; bb[p * 4 + 2] = f.z; bb[p * 4 + 3] = f.w;
        }
#pragma unroll
        for (int rr = 0; rr < 4; rr++)
#pragma unroll
            for (int p = 0; p < 6; p++) {
                float2 f = unpack2(acc[rr][p]);
                mm[(r0 + rr) * 385 + o0 + 2 * p]     = f.x + bb[2 * p];
                mm[(r0 + rr) * 385 + o0 + 2 * p + 1] = f.y + bb[2 * p + 1];
            }
    }
    __syncthreads();

    // ---- Epilogue: delta_v = u*a ; delta_s = b + c*(u.v)
    {
        const float* mm = Xs;
        float* out_ds = out + (size_t)nrows * 384;
        for (int idx = tid; idx < RB * CC; idx += NTHREADS) {
            int r = idx >> 7, c = idx & 127;
            float a  = mm[r * 385 + c];
            float bp = mm[r * 385 + 128 + c];
            float cp = mm[r * 385 + 256 + c];
            float u0 = us[r * 132 + c], u1 = us[(32 + r) * 132 + c], u2 = us[(64 + r) * 132 + c];
            float v0 = vs[r * 132 + c], v1 = vs[(32 + r) * 132 + c], v2 = vs[(64 + r) * 132 + c];
            float dot = u0 * v0 + u1 * v1 + u2 * v2;
            size_t base = (size_t)(row0 + r) * 384 + (size_t)c * 3;
            out[base + 0] = u0 * a;
            out[base + 1] = u1 * a;
            out[base + 2] = u2 * a;
            out_ds[(size_t)(row0 + r) * CC + c] = bp + cp * dot;
        }
    }
}

// ---------------------------------------------------------------------------
extern "C" void kernel_launch(void* const* d_in, const int* in_sizes, int n_in,
                              void* d_out, int out_size) {
    const float* vec = (const float*)d_in[0];  // [N, C, 3]
    const float* sca = (const float*)d_in[1];  // [N, C]
    const float* U   = (const float*)d_in[2];  // [C, C]
    const float* V   = (const float*)d_in[3];  // [C, C]
    const float* W1  = (const float*)d_in[4];  // [C, 2C]
    const float* b1  = (const float*)d_in[5];  // [C]
    const float* W2  = (const float*)d_in[6];  // [3C, C]
    const float* b2  = (const float*)d_in[7];  // [3C]
    float* out = (float*)d_out;

    int nrows = in_sizes[0] / (CC * 3);
    int nblocks = nrows / RB;

    prep_kernel<<<448, 256>>>(U, V, W1, W2);

    cudaFuncSetAttribute(fused_update_kernel,
                         cudaFuncAttributeMaxDynamicSharedMemorySize, SMEM_BYTES);
    fused_update_kernel<<<nblocks, NTHREADS, SMEM_BYTES>>>(vec, sca, b1, b2, out, nrows);
}

// round 3
// speedup vs baseline: 1.3780x; 1.3780x over previous
#include <cuda_runtime.h>
#include <math.h>

#define CC 128
#define RB 32
#define NTHREADS 256

// shared float offsets
#define OFF_MM 0        // Xs (stage/phase1, 12288) aliased with mm (32x388 = 12416)
#define OFF_MS 12416    // ms[k][r] stride 36, k<256  (9216)
#define OFF_HS 21632    // hs[k][r] stride 36, k<128  (4608)
#define SMEM_FLOATS 26240
#define SMEM_BYTES (SMEM_FLOATS * 4)

// transposed weights in device scratch
__device__ float g_Ut[CC * CC];        // Ut[c][o] = U[o][c]
__device__ float g_Vt[CC * CC];
__device__ float g_W1t[2 * CC * CC];   // W1t[k][o]
__device__ float g_W2t[CC * 3 * CC];   // W2t[k][o]

typedef unsigned long long ull;

__device__ __forceinline__ void fma2(ull& d, ull a, ull b) {
    asm("fma.rn.f32x2 %0, %1, %2, %0;" : "+l"(d) : "l"(a), "l"(b));
}
__device__ __forceinline__ ull splat2(float x) {
    ull r; asm("mov.b64 %0, {%1, %1};" : "=l"(r) : "f"(x)); return r;
}
__device__ __forceinline__ float2 unpack2(ull v) {
    float2 f; asm("mov.b64 {%0, %1}, %2;" : "=f"(f.x), "=f"(f.y) : "l"(v)); return f;
}

// ---------------------------------------------------------------------------
__global__ void prep_kernel(const float* __restrict__ U, const float* __restrict__ V,
                            const float* __restrict__ W1, const float* __restrict__ W2) {
    int idx = blockIdx.x * blockDim.x + threadIdx.x;
    if (idx < 16384) {
        int c = idx >> 7, o = idx & 127;
        g_Ut[idx] = U[o * CC + c];
    } else if (idx < 32768) {
        int t = idx - 16384; int c = t >> 7, o = t & 127;
        g_Vt[t] = V[o * CC + c];
    } else if (idx < 65536) {
        int t = idx - 32768; int k = t >> 7, o = t & 127;
        g_W1t[t] = W1[o * 256 + k];
    } else if (idx < 114688) {
        int t = idx - 65536; int k = t / 384, o = t % 384;
        g_W2t[t] = W2[o * CC + k];
    }
}

// one K-pass of phase 1: acc[i][rp][c] (+=) X @ Wt, rows packed in f32x2 pairs
__device__ __forceinline__ void pass_uv(const float* __restrict__ Wt,
                                        const float* __restrict__ Xs,
                                        int r0, int c0, ull acc[3][2][4]) {
#pragma unroll
    for (int i = 0; i < 3; i++)
#pragma unroll
        for (int rp = 0; rp < 2; rp++)
#pragma unroll
            for (int c = 0; c < 4; c++) acc[i][rp][c] = 0ull;

#pragma unroll 2
    for (int k = 0; k < CC; k++) {
        float4 w = __ldg((const float4*)(Wt + k * CC + c0));
        ull ws[4] = {splat2(w.x), splat2(w.y), splat2(w.z), splat2(w.w)};
#pragma unroll
        for (int i = 0; i < 3; i++) {
            ulonglong2 xp = *(const ulonglong2*)(Xs + k * 96 + i * 32 + r0);
#pragma unroll
            for (int c = 0; c < 4; c++) {
                fma2(acc[i][0][c], xp.x, ws[c]);
                fma2(acc[i][1][c], xp.y, ws[c]);
            }
        }
    }
}

// ---------------------------------------------------------------------------
__global__ __launch_bounds__(NTHREADS, 2)
void fused_update_kernel(const float* __restrict__ vec,
                         const float* __restrict__ sca,
                         const float* __restrict__ b1g,
                         const float* __restrict__ b2g,
                         float* __restrict__ out,
                         int nrows) {
    extern __shared__ float sm[];
    float* Xs = sm + OFF_MM;   // phase1 input; aliased as mm in phase3+
    float* ms = sm + OFF_MS;   // [k<256][r], stride 36
    float* hs = sm + OFF_HS;   // [k<128][r], stride 36

    const int tid = threadIdx.x;
    const int tx = tid & 31, ty = tid >> 5;
    const int c0 = tx * 4;     // 4 output channels (phase 1/2 & epilogue)
    const int r0 = ty * 4;     // 4 rows
    const int row0 = blockIdx.x * RB;

    // ---- stage: vec -> Xs[c][i][r]; scalar -> ms[k][r]
    {
        const float4* vg = (const float4*)(vec + (size_t)row0 * 384);
        for (int idx = tid; idx < RB * 96; idx += NTHREADS) {
            int r = idx / 96, q = idx - r * 96;
            float4 f = vg[r * 96 + q];
            float vals[4] = {f.x, f.y, f.z, f.w};
            int e0 = q * 4;
#pragma unroll
            for (int j = 0; j < 4; j++) {
                int e = e0 + j; int c = e / 3, i = e - 3 * c;
                Xs[c * 96 + i * 32 + r] = vals[j];
            }
        }
        for (int idx = tid; idx < RB * CC; idx += NTHREADS) {
            int r = idx >> 7, k = idx & 127;
            ms[k * 36 + r] = sca[(size_t)(row0 + r) * CC + k];
        }
    }
    __syncthreads();

    // ---- Phase 1: two K-passes (U then V) to cap live registers
    ull aU[3][2][4];
    ull dotp[2][4];
    {
        pass_uv(g_Ut, Xs, r0, c0, aU);
        ull aV[3][2][4];
        pass_uv(g_Vt, Xs, r0, c0, aV);

        // dot = u.v (packed) ; vnorm -> ms[128+c][r] ; v dies here
#pragma unroll
        for (int rp = 0; rp < 2; rp++)
#pragma unroll
            for (int c = 0; c < 4; c++) {
                ull d = 0ull;
                fma2(d, aU[0][rp][c], aV[0][rp][c]);
                fma2(d, aU[1][rp][c], aV[1][rp][c]);
                fma2(d, aU[2][rp][c], aV[2][rp][c]);
                dotp[rp][c] = d;
                ull s = splat2(1e-8f);
                fma2(s, aV[0][rp][c], aV[0][rp][c]);
                fma2(s, aV[1][rp][c], aV[1][rp][c]);
                fma2(s, aV[2][rp][c], aV[2][rp][c]);
                float2 sv = unpack2(s);
                ms[(128 + c0 + c) * 36 + r0 + 2 * rp]     = sqrtf(sv.x);
                ms[(128 + c0 + c) * 36 + r0 + 2 * rp + 1] = sqrtf(sv.y);
            }
    }
    __syncthreads();

    // ---- Phase 2: h = silu(m @ W1t + b1), K=256, out [32 x 128]
    {
        ull acc[2][4];
#pragma unroll
        for (int rp = 0; rp < 2; rp++)
#pragma unroll
            for (int c = 0; c < 4; c++) acc[rp][c] = 0ull;

#pragma unroll 2
        for (int k = 0; k < 2 * CC; k++) {
            ulonglong2 xp = *(const ulonglong2*)(ms + k * 36 + r0);
            float4 w = __ldg((const float4*)(g_W1t + k * CC + c0));
            ull ws[4] = {splat2(w.x), splat2(w.y), splat2(w.z), splat2(w.w)};
#pragma unroll
            for (int c = 0; c < 4; c++) {
                fma2(acc[0][c], xp.x, ws[c]);
                fma2(acc[1][c], xp.y, ws[c]);
            }
        }
        float4 bias = __ldg((const float4*)(b1g + c0));
        float bb[4] = {bias.x, bias.y, bias.z, bias.w};
#pragma unroll
        for (int rp = 0; rp < 2; rp++)
#pragma unroll
            for (int c = 0; c < 4; c++) {
                float2 f = unpack2(acc[rp][c]);
                float x0 = f.x + bb[c], x1 = f.y + bb[c];
                hs[(c0 + c) * 36 + r0 + 2 * rp]     = x0 / (1.0f + __expf(-x0));
                hs[(c0 + c) * 36 + r0 + 2 * rp + 1] = x1 / (1.0f + __expf(-x1));
            }
    }
    __syncthreads();

    // ---- Phase 3: mm = h @ W2t + b2, K=128, out [32 x 384] (cols packed)
    {
        const int o0 = tx * 12;
        ull acc[4][6];
#pragma unroll
        for (int r = 0; r < 4; r++)
#pragma unroll
            for (int p = 0; p < 6; p++) acc[r][p] = 0ull;

#pragma unroll 2
        for (int k = 0; k < CC; k++) {
            float4 xv = *(const float4*)(hs + k * 36 + r0);
            ull xs[4] = {splat2(xv.x), splat2(xv.y), splat2(xv.z), splat2(xv.w)};
            const float* wrow = g_W2t + k * 384 + o0;
            ulonglong2 w0 = __ldg((const ulonglong2*)(wrow));
            ulonglong2 w1 = __ldg((const ulonglong2*)(wrow + 4));
            ulonglong2 w2 = __ldg((const ulonglong2*)(wrow + 8));
            ull wp[6] = {w0.x, w0.y, w1.x, w1.y, w2.x, w2.y};
#pragma unroll
            for (int r = 0; r < 4; r++)
#pragma unroll
                for (int p = 0; p < 6; p++) fma2(acc[r][p], xs[r], wp[p]);
        }
        float* mm = Xs;  // alias (Xs dead)
        float bb[12];
#pragma unroll
        for (int p = 0; p < 3; p++) {
            float4 f = __ldg((const float4*)(b2g + o0 + p * 4));
            bb[p * 4 + 0] = f.x; bb[p * 4 + 1] = f.y;
            bb[p * 4 + 2] = f.z; bb[p * 4 + 3] = f.w;
        }
#pragma unroll
        for (int r = 0; r < 4; r++)
#pragma unroll
            for (int p = 0; p < 6; p++) {
                float2 f = unpack2(acc[r][p]);
                float2 o = make_float2(f.x + bb[2 * p], f.y + bb[2 * p + 1]);
                *(float2*)(mm + (r0 + r) * 388 + o0 + 2 * p) = o;
            }
    }
    __syncthreads();

    // ---- Epilogue: delta_v = u*a ; delta_s = b + c*dot   (u, dot in regs)
    {
        const float* mm = Xs;
        float* out_ds = out + (size_t)nrows * 384;
#pragma unroll
        for (int r = 0; r < 4; r++) {
            const int rp = r >> 1, hl = r & 1;
            const int rr = r0 + r;
            float4 a4 = *(const float4*)(mm + rr * 388 + c0);
            float4 b4 = *(const float4*)(mm + rr * 388 + 128 + c0);
            float4 c4 = *(const float4*)(mm + rr * 388 + 256 + c0);
            float av[4] = {a4.x, a4.y, a4.z, a4.w};
            float bv[4] = {b4.x, b4.y, b4.z, b4.w};
            float cv[4] = {c4.x, c4.y, c4.z, c4.w};

            float o12[12], ds[4];
#pragma unroll
            for (int c = 0; c < 4; c++) {
                float2 d = unpack2(dotp[rp][c]);
                float dv = hl ? d.y : d.x;
                ds[c] = bv[c] + cv[c] * dv;
#pragma unroll
                for (int i = 0; i < 3; i++) {
                    float2 t = unpack2(aU[i][rp][c]);
                    float uval = hl ? t.y : t.x;
                    o12[c * 3 + i] = uval * av[c];
                }
            }
            float4* op = (float4*)(out + (size_t)(row0 + rr) * 384 + (size_t)c0 * 3);
            op[0] = make_float4(o12[0], o12[1], o12[2],  o12[3]);
            op[1] = make_float4(o12[4], o12[5], o12[6],  o12[7]);
            op[2] = make_float4(o12[8], o12[9], o12[10], o12[11]);
            *(float4*)(out_ds + (size_t)(row0 + rr) * CC + c0) =
                make_float4(ds[0], ds[1], ds[2], ds[3]);
        }
    }
}

// ---------------------------------------------------------------------------
extern "C" void kernel_launch(void* const* d_in, const int* in_sizes, int n_in,
                              void* d_out, int out_size) {
    const float* vec = (const float*)d_in[0];
    const float* sca = (const float*)d_in[1];
    const float* U   = (const float*)d_in[2];
    const float* V   = (const float*)d_in[3];
    const float* W1  = (const float*)d_in[4];
    const float* b1  = (const float*)d_in[5];
    const float* W2  = (const float*)d_in[6];
    const float* b2  = (const float*)d_in[7];
    float* out = (float*)d_out;

    int nrows = in_sizes[0] / (CC * 3);
    int nblocks = nrows / RB;

    prep_kernel<<<448, 256>>>(U, V, W1, W2);

    cudaFuncSetAttribute(fused_update_kernel,
                         cudaFuncAttributeMaxDynamicSharedMemorySize, SMEM_BYTES);
    fused_update_kernel<<<nblocks, NTHREADS, SMEM_BYTES>>>(vec, sca, b1, b2, out, nrows);
}